// round 12
// baseline (speedup 1.0000x reference)
#include <cuda_runtime.h>
#include <cuda_bf16.h>
#include <mma.h>

using namespace nvcuda;

#define NTILES 128
#define C_DIM  256
#define I_DIM  128
#define HW_DIM 1024
#define KP_DIM 256

// Scratch (static device globals)
__device__ __nv_bfloat16 g_phi  [(size_t)NTILES * I_DIM * KP_DIM];  // [tile][i][k]
__device__ __nv_bfloat16 g_gg   [(size_t)NTILES * I_DIM * KP_DIM];  // [tile][i][k]
// Pre-converted bf16 weights
__device__ __nv_bfloat16 g_twb[I_DIM * C_DIM];
__device__ __nv_bfloat16 g_pwb[I_DIM * C_DIM];
__device__ __nv_bfloat16 g_gwb[I_DIM * C_DIM];
__device__ __nv_bfloat16 g_wwb[C_DIM * I_DIM];

// ---------------------------------------------------------------------------
// Kernel 0: convert all weights f32 -> bf16 once per launch.
// ---------------------------------------------------------------------------
__global__ void prep_kernel(const float* __restrict__ tw, const float* __restrict__ pw,
                            const float* __restrict__ gw, const float* __restrict__ ww)
{
    int i = blockIdx.x * blockDim.x + threadIdx.x;   // 0..32767
    if (i < I_DIM * C_DIM) {
        g_twb[i] = __float2bfloat16(tw[i]);
        g_pwb[i] = __float2bfloat16(pw[i]);
        g_gwb[i] = __float2bfloat16(gw[i]);
        g_wwb[i] = __float2bfloat16(ww[i]);
    }
}

// ---------------------------------------------------------------------------
// Kernel 1: phi/g 1x1 convs + fused 2x2 maxpool (unchanged from round 9).
// grid = (nb:8, tile:128), 256 threads, 2 CTAs/SM.
// ---------------------------------------------------------------------------
#define CB_LDB 136
#define CB_LDA 72
#define CB_LDU 36

__global__ __launch_bounds__(256, 2) void conv2_kernel(
    const float* __restrict__ x,
    const float* __restrict__ pb, const float* __restrict__ gb)
{
    extern __shared__ char smem[];
    __nv_bfloat16* sB = reinterpret_cast<__nv_bfloat16*>(smem);              // [256][136]
    __nv_bfloat16* sA = reinterpret_cast<__nv_bfloat16*>(smem + 69632);      // [128][72]
    float*         bufAll = reinterpret_cast<float*>(smem + 88064);          // 8*[16][36]

    const int nb   = blockIdx.x;
    const int tile = blockIdx.y;
    const int b = tile >> 4, t = tile & 15;
    const int bs1 = t >> 2, bs2 = t & 3;
    const int tid = threadIdx.x;
    const int warp = tid >> 5, lane = tid & 31;
    const int wr = warp >> 1, wc = warp & 1;
    float* bufW = bufAll + warp * 16 * CB_LDU;

    const float* xbase = x + (size_t)b * C_DIM * 16384 + bs1 * 32 * 128 + bs2 * 32;
    const int p0 = nb * 4;

    #pragma unroll
    for (int it = 0; it < 32; it++) {
        int lin = it * 256 + tid;
        int r  = lin >> 5;
        int j4 = (lin & 31) * 4;
        int pp = p0 + (j4 >> 5);
        int qq = j4 & 31;
        float4 v = *reinterpret_cast<const float4*>(
            xbase + (size_t)r * 16384 + pp * 128 + qq);
        __nv_bfloat16* d = sB + r * CB_LDB + j4;
        *reinterpret_cast<__nv_bfloat162*>(d)     = __floats2bfloat162_rn(v.x, v.y);
        *reinterpret_cast<__nv_bfloat162*>(d + 2) = __floats2bfloat162_rn(v.z, v.w);
    }

    const __nv_bfloat16* Ws[2] = {g_pwb, g_gwb};
    const float* Bs[2] = {pb, gb};

    for (int mb = 0; mb < 2; mb++) {
        const __nv_bfloat16* W = Ws[mb];
        const float* BV = Bs[mb];

        wmma::fragment<wmma::accumulator, 16, 16, 16, float> acc[2][4];
        #pragma unroll
        for (int i = 0; i < 2; i++)
            #pragma unroll
            for (int j = 0; j < 4; j++) wmma::fill_fragment(acc[i][j], 0.0f);

        for (int kc = 0; kc < 4; kc++) {
            __syncthreads();
            #pragma unroll
            for (int it = 0; it < 4; it++) {
                int lin = it * 256 + tid;
                int r = lin >> 3, c8 = (lin & 7) * 8;
                *reinterpret_cast<uint4*>(sA + r * CB_LDA + c8) =
                    *reinterpret_cast<const uint4*>(W + r * C_DIM + kc * 64 + c8);
            }
            __syncthreads();
            #pragma unroll
            for (int kk = 0; kk < 4; kk++) {
                wmma::fragment<wmma::matrix_a, 16, 16, 16, __nv_bfloat16, wmma::row_major> fa[2];
                #pragma unroll
                for (int i = 0; i < 2; i++)
                    wmma::load_matrix_sync(fa[i], sA + (wr * 32 + i * 16) * CB_LDA + kk * 16, CB_LDA);
                #pragma unroll
                for (int j = 0; j < 4; j++) {
                    wmma::fragment<wmma::matrix_b, 16, 16, 16, __nv_bfloat16, wmma::row_major> fb;
                    wmma::load_matrix_sync(fb,
                        sB + (kc * 64 + kk * 16) * CB_LDB + wc * 64 + j * 16, CB_LDB);
                    #pragma unroll
                    for (int i = 0; i < 2; i++)
                        wmma::mma_sync(acc[i][j], fa[i], fb, acc[i][j]);
                }
            }
        }

        for (int i = 0; i < 2; i++) {
            int o0 = wr * 32 + i * 16;
            float hm[8];
            #pragma unroll
            for (int jh = 0; jh < 2; jh++) {
                wmma::store_matrix_sync(bufW,      acc[i][jh * 2],     CB_LDU, wmma::mem_row_major);
                wmma::store_matrix_sync(bufW + 16, acc[i][jh * 2 + 1], CB_LDU, wmma::mem_row_major);
                __syncwarp();
                #pragma unroll
                for (int e = 0; e < 8; e++) {
                    int idx = e * 32 + lane;
                    int r = idx >> 4, s = idx & 15;
                    float mv = fmaxf(bufW[r * CB_LDU + 2 * s], bufW[r * CB_LDU + 2 * s + 1]);
                    hm[e] = (jh == 0) ? mv : fmaxf(hm[e], mv);
                }
                __syncwarp();
            }
            __nv_bfloat16* dst = ((mb == 0) ? g_phi : g_gg) + (size_t)tile * I_DIM * KP_DIM;
            const int prow = nb * 2 + wc;
            #pragma unroll
            for (int e = 0; e < 8; e++) {
                int idx = e * 32 + lane;
                int r = idx >> 4, s = idx & 15;
                dst[(o0 + r) * KP_DIM + prow * 16 + s] = __float2bfloat16(hm[e] + BV[o0 + r]);
            }
        }
    }
}

// ---------------------------------------------------------------------------
// Kernel 2 (FUSED, 64-query slice, 2 CTAs/SM).
// grid = (qb:16, tile:128), 256 threads (8 warps), smem 110592B.
// Layout (offsets):
//   sT   @0      : theta [128i][72] (18432); later y [64q][136] (17408)
//   R    @18432  : phase0 sX [256c][72] (36864) + sWt [128][136] @55296
//                  phase1+ sS [64q][264] (33792) + sPc/sGc [128][136] @52224
//                  phase2b sW [256o][136] (69632)
//   buf  @90112  : 8 * [16][36] f32 (18432)
//   bn   @108544 : sScale[256] + sBase[256]
// ---------------------------------------------------------------------------
#define A2_LDT  72     // theta ld
#define A2_LDX  72     // x ld
#define A2_LDC  136    // Wt/phi/g chunk ld, W ld, y ld
#define A2_LDS  264    // S ld
#define A2_LDU  36

__global__ __launch_bounds__(256, 2) void attn_kernel(
    const float* __restrict__ x, const float* __restrict__ tb,
    const float* __restrict__ wb,
    const float* __restrict__ gam, const float* __restrict__ bet,
    const float* __restrict__ mean, const float* __restrict__ var,
    float* __restrict__ out)
{
    extern __shared__ char smem[];
    __nv_bfloat16* sT  = reinterpret_cast<__nv_bfloat16*>(smem);             // theta / y
    __nv_bfloat16* sX  = reinterpret_cast<__nv_bfloat16*>(smem + 18432);     // [256][72]
    __nv_bfloat16* sWt = reinterpret_cast<__nv_bfloat16*>(smem + 55296);     // [128][136]
    __nv_bfloat16* sS  = reinterpret_cast<__nv_bfloat16*>(smem + 18432);     // [64][264]
    __nv_bfloat16* sPc = reinterpret_cast<__nv_bfloat16*>(smem + 52224);     // [128][136]
    __nv_bfloat16* sW  = reinterpret_cast<__nv_bfloat16*>(smem + 18432);     // [256][136]
    float*         bufAll = reinterpret_cast<float*>(smem + 90112);          // 8*[16][36]
    float*         sScale = reinterpret_cast<float*>(smem + 108544);         // [256]
    float*         sBase  = reinterpret_cast<float*>(smem + 109568);         // [256]

    const int qb   = blockIdx.x;                    // 0..15, 64 queries each
    const int tile = blockIdx.y;
    const int b = tile >> 4, t = tile & 15;
    const int bs1 = t >> 2, bs2 = t & 3;
    const int tid = threadIdx.x;
    const int warp = tid >> 5, lane = tid & 31;
    float* bufW = bufAll + warp * 16 * A2_LDU;

    // BN constants (one channel per thread)
    {
        float sc = gam[tid] * rsqrtf(var[tid] + 1e-5f);
        sScale[tid] = sc;
        sBase[tid]  = (wb[tid] - mean[tid]) * sc + bet[tid];
    }

    // ---- Phase 0: stage x slice [256c][64q] f32 -> bf16 ----
    const float* xtile = x + (size_t)b * C_DIM * 16384 + bs1 * 32 * 128 + bs2 * 32
                       + (size_t)qb * 256;   // hw = qb*64 + lq; offset qb*256 + (lq>>5)*128 + (lq&31)
    #pragma unroll
    for (int it = 0; it < 16; it++) {
        int lin = it * 256 + tid;                   // float4 idx among 4096
        int r  = lin >> 4;                          // channel 0..255
        int j4 = (lin & 15) * 4;                    // local q (mult of 4)
        float4 v = *reinterpret_cast<const float4*>(
            xtile + (size_t)r * 16384 + (j4 >> 5) * 128 + (j4 & 31));
        __nv_bfloat16* d = sX + r * A2_LDX + j4;
        *reinterpret_cast<__nv_bfloat162*>(d)     = __floats2bfloat162_rn(v.x, v.y);
        *reinterpret_cast<__nv_bfloat162*>(d + 2) = __floats2bfloat162_rn(v.z, v.w);
    }

    // GEMM0: theta[128i, 64q] = Wt @ x + tb; warp grid 4i x 2q (32x32 tiles)
    {
        const int i0w = (warp >> 1) * 32;
        const int q0w = (warp & 1) * 32;
        wmma::fragment<wmma::accumulator, 16, 16, 16, float> acc0[2][2];
        #pragma unroll
        for (int i = 0; i < 2; i++)
            #pragma unroll
            for (int j = 0; j < 2; j++) wmma::fill_fragment(acc0[i][j], 0.0f);

        for (int kc = 0; kc < 2; kc++) {
            __syncthreads();   // (kc=0: sX staged by all; kc=1: prev sWt reads done)
            #pragma unroll
            for (int it = 0; it < 8; it++) {
                int lin = it * 256 + tid;           // uint4 among 2048
                int r = lin >> 4, c8 = (lin & 15) * 8;
                *reinterpret_cast<uint4*>(sWt + r * A2_LDC + c8) =
                    *reinterpret_cast<const uint4*>(g_twb + r * C_DIM + kc * 128 + c8);
            }
            __syncthreads();
            #pragma unroll
            for (int kk = 0; kk < 8; kk++) {
                wmma::fragment<wmma::matrix_a, 16, 16, 16, __nv_bfloat16, wmma::row_major> fa[2];
                wmma::fragment<wmma::matrix_b, 16, 16, 16, __nv_bfloat16, wmma::row_major> fb[2];
                #pragma unroll
                for (int i = 0; i < 2; i++)
                    wmma::load_matrix_sync(fa[i], sWt + (i0w + i * 16) * A2_LDC + kk * 16, A2_LDC);
                #pragma unroll
                for (int j = 0; j < 2; j++)
                    wmma::load_matrix_sync(fb[j], sX + (kc * 128 + kk * 16) * A2_LDX + q0w + j * 16, A2_LDX);
                #pragma unroll
                for (int i = 0; i < 2; i++)
                    #pragma unroll
                    for (int j = 0; j < 2; j++)
                        wmma::mma_sync(acc0[i][j], fa[i], fb[j], acc0[i][j]);
            }
        }
        // stream theta + bias -> sT [i][q] bf16 (ld 72)
        for (int i = 0; i < 2; i++) {
            int i0 = i0w + i * 16;
            wmma::store_matrix_sync(bufW,      acc0[i][0], A2_LDU, wmma::mem_row_major);
            wmma::store_matrix_sync(bufW + 16, acc0[i][1], A2_LDU, wmma::mem_row_major);
            __syncwarp();
            #pragma unroll
            for (int e = 0; e < 8; e++) {
                int pidx = e * 32 + lane;           // 256 pairs in 16x32
                int r = pidx >> 4, col = (pidx & 15) * 2;
                float bias = tb[i0 + r];
                *reinterpret_cast<__nv_bfloat162*>(sT + (i0 + r) * A2_LDT + q0w + col) =
                    __floats2bfloat162_rn(bufW[r * A2_LDU + col] + bias,
                                          bufW[r * A2_LDU + col + 1] + bias);
            }
            __syncwarp();
        }
    }
    __syncthreads();   // theta complete; sX/sWt dead

    // ---- Phase 1: S[64q,256k] = theta^T @ phi, phi in 2 k-chunks ----
    {
        const int q0w = (warp >> 2) * 32;
        const int k0w = (warp & 3) * 32;
        const __nv_bfloat16* ps = g_phi + (size_t)tile * I_DIM * KP_DIM;
        for (int kc = 0; kc < 2; kc++) {
            if (kc) __syncthreads();                // prev chunk reads done
            #pragma unroll
            for (int it = 0; it < 8; it++) {
                int lin = it * 256 + tid;           // uint4 among 2048
                int r = lin >> 4, c8 = (lin & 15) * 8;
                *reinterpret_cast<uint4*>(sPc + r * A2_LDC + c8) =
                    *reinterpret_cast<const uint4*>(ps + r * KP_DIM + kc * 128 + c8);
            }
            __syncthreads();
            wmma::fragment<wmma::accumulator, 16, 16, 16, float> acc1[2][2];
            #pragma unroll
            for (int i = 0; i < 2; i++)
                #pragma unroll
                for (int j = 0; j < 2; j++) wmma::fill_fragment(acc1[i][j], 0.0f);
            #pragma unroll
            for (int kk = 0; kk < 8; kk++) {
                wmma::fragment<wmma::matrix_a, 16, 16, 16, __nv_bfloat16, wmma::col_major> fa[2];
                wmma::fragment<wmma::matrix_b, 16, 16, 16, __nv_bfloat16, wmma::row_major> fb[2];
                #pragma unroll
                for (int i = 0; i < 2; i++)
                    wmma::load_matrix_sync(fa[i], sT + (kk * 16) * A2_LDT + q0w + i * 16, A2_LDT);
                #pragma unroll
                for (int j = 0; j < 2; j++)
                    wmma::load_matrix_sync(fb[j], sPc + (kk * 16) * A2_LDC + k0w + j * 16, A2_LDC);
                #pragma unroll
                for (int i = 0; i < 2; i++)
                    #pragma unroll
                    for (int j = 0; j < 2; j++)
                        wmma::mma_sync(acc1[i][j], fa[i], fb[j], acc1[i][j]);
            }
            // stream S chunk -> bf16 sS[q][kc*128 + k0w ...]
            for (int i = 0; i < 2; i++) {
                int q0 = q0w + i * 16;
                wmma::store_matrix_sync(bufW,      acc1[i][0], A2_LDU, wmma::mem_row_major);
                wmma::store_matrix_sync(bufW + 16, acc1[i][1], A2_LDU, wmma::mem_row_major);
                __syncwarp();
                #pragma unroll
                for (int e = 0; e < 8; e++) {
                    int pidx = e * 32 + lane;
                    int r = pidx >> 4, col = (pidx & 15) * 2;
                    *reinterpret_cast<__nv_bfloat162*>(
                        sS + (q0 + r) * A2_LDS + kc * 128 + k0w + col) =
                        __floats2bfloat162_rn(bufW[r * A2_LDU + col], bufW[r * A2_LDU + col + 1]);
                }
                __syncwarp();
            }
        }
    }
    __syncthreads();

    // softmax: 8 warps x 8 rows, k=256
    for (int rr = 0; rr < 8; rr++) {
        int row = warp * 8 + rr;
        float v[8];
        float m = -1e30f;
        #pragma unroll
        for (int u = 0; u < 8; u++) {
            v[u] = __bfloat162float(sS[row * A2_LDS + u * 32 + lane]);
            m = fmaxf(m, v[u]);
        }
        #pragma unroll
        for (int off = 16; off > 0; off >>= 1) m = fmaxf(m, __shfl_xor_sync(0xffffffffu, m, off));
        float ssum = 0.f;
        #pragma unroll
        for (int u = 0; u < 8; u++) { v[u] = __expf(v[u] - m); ssum += v[u]; }
        #pragma unroll
        for (int off = 16; off > 0; off >>= 1) ssum += __shfl_xor_sync(0xffffffffu, ssum, off);
        float inv = 1.0f / ssum;
        #pragma unroll
        for (int u = 0; u < 8; u++)
            sS[row * A2_LDS + u * 32 + lane] = __float2bfloat16(v[u] * inv);
    }
    __syncthreads();

    // ---- Phase 2: y[64q,128io] = F @ g^T, g in 2 k-chunks ----
    {
        const int q0w  = (warp >> 2) * 32;
        const int io0w = (warp & 3) * 32;
        const __nv_bfloat16* gs = g_gg + (size_t)tile * I_DIM * KP_DIM;
        wmma::fragment<wmma::accumulator, 16, 16, 16, float> acc2[2][2];
        #pragma unroll
        for (int i = 0; i < 2; i++)
            #pragma unroll
            for (int j = 0; j < 2; j++) wmma::fill_fragment(acc2[i][j], 0.0f);
        for (int kc = 0; kc < 2; kc++) {
            if (kc) __syncthreads();
            #pragma unroll
            for (int it = 0; it < 8; it++) {
                int lin = it * 256 + tid;
                int r = lin >> 4, c8 = (lin & 15) * 8;
                *reinterpret_cast<uint4*>(sPc + r * A2_LDC + c8) =
                    *reinterpret_cast<const uint4*>(gs + r * KP_DIM + kc * 128 + c8);
            }
            __syncthreads();
            #pragma unroll
            for (int kk = 0; kk < 8; kk++) {
                wmma::fragment<wmma::matrix_a, 16, 16, 16, __nv_bfloat16, wmma::row_major> fa[2];
                wmma::fragment<wmma::matrix_b, 16, 16, 16, __nv_bfloat16, wmma::col_major> fb[2];
                #pragma unroll
                for (int i = 0; i < 2; i++)
                    wmma::load_matrix_sync(fa[i], sS + (q0w + i * 16) * A2_LDS + kc * 128 + kk * 16, A2_LDS);
                #pragma unroll
                for (int j = 0; j < 2; j++)
                    wmma::load_matrix_sync(fb[j], sPc + (io0w + j * 16) * A2_LDC + kk * 16, A2_LDC);
                #pragma unroll
                for (int i = 0; i < 2; i++)
                    #pragma unroll
                    for (int j = 0; j < 2; j++)
                        wmma::mma_sync(acc2[i][j], fa[i], fb[j], acc2[i][j]);
            }
        }
        // stream y -> sT as [64q][136] bf16 (theta dead)
        for (int i = 0; i < 2; i++) {
            int q0 = q0w + i * 16;
            wmma::store_matrix_sync(bufW,      acc2[i][0], A2_LDU, wmma::mem_row_major);
            wmma::store_matrix_sync(bufW + 16, acc2[i][1], A2_LDU, wmma::mem_row_major);
            __syncwarp();
            #pragma unroll
            for (int e = 0; e < 8; e++) {
                int pidx = e * 32 + lane;
                int r = pidx >> 4, col = (pidx & 15) * 2;
                *reinterpret_cast<__nv_bfloat162*>(sT + (q0 + r) * A2_LDC + io0w + col) =
                    __floats2bfloat162_rn(bufW[r * A2_LDU + col], bufW[r * A2_LDU + col + 1]);
            }
            __syncwarp();
        }
    }
    __syncthreads();   // y complete; sS/sPc dead

    // stage W [256][128] bf16 into sW
    #pragma unroll
    for (int it = 0; it < 16; it++) {
        int lin = it * 256 + tid;               // uint4 among 4096
        int r = lin >> 4, c8 = (lin & 15) * 8;
        *reinterpret_cast<uint4*>(sW + r * A2_LDC + c8) =
            *reinterpret_cast<const uint4*>(g_wwb + r * I_DIM + c8);
    }
    __syncthreads();

    // GEMM3: wy[256o, 64q] = W @ y^T; warp grid 4o x 2q (64x32 tiles)
    {
        const int o0w = (warp >> 1) * 64;
        const int q0w = (warp & 1) * 32;
        wmma::fragment<wmma::accumulator, 16, 16, 16, float> acc3[4][2];
        #pragma unroll
        for (int i = 0; i < 4; i++)
            #pragma unroll
            for (int j = 0; j < 2; j++) wmma::fill_fragment(acc3[i][j], 0.0f);
        #pragma unroll
        for (int kk = 0; kk < 8; kk++) {
            wmma::fragment<wmma::matrix_b, 16, 16, 16, __nv_bfloat16, wmma::col_major> fb[2];
            #pragma unroll
            for (int j = 0; j < 2; j++)
                wmma::load_matrix_sync(fb[j], sT + (q0w + j * 16) * A2_LDC + kk * 16, A2_LDC);
            #pragma unroll
            for (int i = 0; i < 4; i++) {
                wmma::fragment<wmma::matrix_a, 16, 16, 16, __nv_bfloat16, wmma::row_major> fa;
                wmma::load_matrix_sync(fa, sW + (o0w + i * 16) * A2_LDC + kk * 16, A2_LDC);
                #pragma unroll
                for (int j = 0; j < 2; j++)
                    wmma::mma_sync(acc3[i][j], fa, fb[j], acc3[i][j]);
            }
        }

        // epilogue: BN + residual + permuted coalesced store
        // hw = qb*64 + lq; oh = (o&15)*8 + (qb>>1); ow = (qb&1)*64 + lq
        const float* xrow = xtile;       // already offset by qb*256
        float* obase = out + (size_t)b * C_DIM * 16384;
        const int lq = q0w + lane;
        const int xoff = (lq >> 5) * 128 + (lq & 31);
        const int owbase = (qb & 1) * 64 + lq;
        const int ohq = qb >> 1;
        for (int i = 0; i < 4; i++) {
            int o0 = o0w + i * 16;
            wmma::store_matrix_sync(bufW,      acc3[i][0], A2_LDU, wmma::mem_row_major);
            wmma::store_matrix_sync(bufW + 16, acc3[i][1], A2_LDU, wmma::mem_row_major);
            __syncwarp();
            #pragma unroll
            for (int e = 0; e < 16; e++) {
                int o = o0 + e;
                float v = bufW[e * A2_LDU + lane] * sScale[o] + sBase[o]
                        + xrow[(size_t)o * 16384 + xoff];
                int co = t * 16 + (o >> 4);
                int oh = (o & 15) * 8 + ohq;
                obase[(size_t)co * 16384 + (size_t)oh * 128 + owbase] = v;
            }
            __syncwarp();
        }
    }
}

// ---------------------------------------------------------------------------
extern "C" void kernel_launch(void* const* d_in, const int* in_sizes, int n_in,
                              void* d_out, int out_size)
{
    const float* x    = (const float*)d_in[0];
    const float* tw   = (const float*)d_in[1];
    const float* tb   = (const float*)d_in[2];
    const float* pw   = (const float*)d_in[3];
    const float* pb   = (const float*)d_in[4];
    const float* gw   = (const float*)d_in[5];
    const float* gb   = (const float*)d_in[6];
    const float* ww   = (const float*)d_in[7];
    const float* wb   = (const float*)d_in[8];
    const float* gam  = (const float*)d_in[9];
    const float* bet  = (const float*)d_in[10];
    const float* mean = (const float*)d_in[11];
    const float* var  = (const float*)d_in[12];
    float* out = (float*)d_out;

    cudaFuncSetAttribute(conv2_kernel, cudaFuncAttributeMaxDynamicSharedMemorySize, 106496);
    cudaFuncSetAttribute(attn_kernel,  cudaFuncAttributeMaxDynamicSharedMemorySize, 110592);

    prep_kernel <<<128, 256>>>(tw, pw, gw, ww);
    conv2_kernel<<<dim3(8, NTILES),  256, 106496>>>(x, pb, gb);
    attn_kernel <<<dim3(16, NTILES), 256, 110592>>>(x, tb, wb, gam, bet, mean, var, out);
}

// round 17
// speedup vs baseline: 1.5484x; 1.5484x over previous
#include <cuda_runtime.h>
#include <cuda_bf16.h>
#include <mma.h>
#include <cstdint>

using namespace nvcuda;

#define NTILES 128
#define C_DIM  256
#define I_DIM  128
#define HW_DIM 1024
#define KP_DIM 256

// cp.async helpers (16B, .cg = L2-only fill, straight to smem)
__device__ __forceinline__ void cpa16(unsigned int dst_smem, const void* src) {
    asm volatile("cp.async.cg.shared.global [%0], [%1], 16;" :: "r"(dst_smem), "l"(src));
}
#define CP_COMMIT_WAIT() asm volatile("cp.async.commit_group;\ncp.async.wait_group 0;" ::: "memory")

// Scratch (static device globals)
__device__ __nv_bfloat16 g_phi  [(size_t)NTILES * I_DIM * KP_DIM];  // [tile][i][k]
__device__ __nv_bfloat16 g_gg   [(size_t)NTILES * I_DIM * KP_DIM];  // [tile][i][k]
// Pre-converted bf16 weights
__device__ __nv_bfloat16 g_twb[I_DIM * C_DIM];
__device__ __nv_bfloat16 g_pwb[I_DIM * C_DIM];
__device__ __nv_bfloat16 g_gwb[I_DIM * C_DIM];
__device__ __nv_bfloat16 g_wwb[C_DIM * I_DIM];

// ---------------------------------------------------------------------------
// Kernel 0: convert all weights f32 -> bf16 once per launch.
// ---------------------------------------------------------------------------
__global__ void prep_kernel(const float* __restrict__ tw, const float* __restrict__ pw,
                            const float* __restrict__ gw, const float* __restrict__ ww)
{
    int i = blockIdx.x * blockDim.x + threadIdx.x;   // 0..32767
    if (i < I_DIM * C_DIM) {
        g_twb[i] = __float2bfloat16(tw[i]);
        g_pwb[i] = __float2bfloat16(pw[i]);
        g_gwb[i] = __float2bfloat16(gw[i]);
        g_wwb[i] = __float2bfloat16(ww[i]);
    }
}

// ---------------------------------------------------------------------------
// Kernel 1: phi/g 1x1 convs + fused 2x2 maxpool.
// grid = (nb:8, tile:128), 256 threads, 2 CTAs/SM.
// ---------------------------------------------------------------------------
#define CB_LDB 136
#define CB_LDA 72
#define CB_LDU 36

__global__ __launch_bounds__(256, 2) void conv2_kernel(
    const float* __restrict__ x,
    const float* __restrict__ pb, const float* __restrict__ gb)
{
    extern __shared__ char smem[];
    __nv_bfloat16* sB = reinterpret_cast<__nv_bfloat16*>(smem);              // [256][136]
    __nv_bfloat16* sA = reinterpret_cast<__nv_bfloat16*>(smem + 69632);      // [128][72]
    float*         bufAll = reinterpret_cast<float*>(smem + 88064);          // 8*[16][36]
    const unsigned int smem_u32 = (unsigned int)__cvta_generic_to_shared(smem);
    const unsigned int sA_u32 = smem_u32 + 69632;

    const int nb   = blockIdx.x;
    const int tile = blockIdx.y;
    const int b = tile >> 4, t = tile & 15;
    const int bs1 = t >> 2, bs2 = t & 3;
    const int tid = threadIdx.x;
    const int warp = tid >> 5, lane = tid & 31;
    const int wr = warp >> 1, wc = warp & 1;
    float* bufW = bufAll + warp * 16 * CB_LDU;

    const float* xbase = x + (size_t)b * C_DIM * 16384 + bs1 * 32 * 128 + bs2 * 32;
    const int p0 = nb * 4;

    #pragma unroll
    for (int it = 0; it < 32; it++) {
        int lin = it * 256 + tid;
        int r  = lin >> 5;
        int j4 = (lin & 31) * 4;
        int pp = p0 + (j4 >> 5);
        int qq = j4 & 31;
        float4 v = *reinterpret_cast<const float4*>(
            xbase + (size_t)r * 16384 + pp * 128 + qq);
        __nv_bfloat16* d = sB + r * CB_LDB + j4;
        *reinterpret_cast<__nv_bfloat162*>(d)     = __floats2bfloat162_rn(v.x, v.y);
        *reinterpret_cast<__nv_bfloat162*>(d + 2) = __floats2bfloat162_rn(v.z, v.w);
    }

    const __nv_bfloat16* Ws[2] = {g_pwb, g_gwb};
    const float* Bs[2] = {pb, gb};

    for (int mb = 0; mb < 2; mb++) {
        const __nv_bfloat16* W = Ws[mb];
        const float* BV = Bs[mb];

        wmma::fragment<wmma::accumulator, 16, 16, 16, float> acc[2][4];
        #pragma unroll
        for (int i = 0; i < 2; i++)
            #pragma unroll
            for (int j = 0; j < 4; j++) wmma::fill_fragment(acc[i][j], 0.0f);

        for (int kc = 0; kc < 4; kc++) {
            __syncthreads();
            #pragma unroll
            for (int it = 0; it < 4; it++) {
                int lin = it * 256 + tid;
                int r = lin >> 3, c8 = (lin & 7) * 8;
                cpa16(sA_u32 + (r * CB_LDA + c8) * 2, W + r * C_DIM + kc * 64 + c8);
            }
            CP_COMMIT_WAIT();
            __syncthreads();
            #pragma unroll
            for (int kk = 0; kk < 4; kk++) {
                wmma::fragment<wmma::matrix_a, 16, 16, 16, __nv_bfloat16, wmma::row_major> fa[2];
                #pragma unroll
                for (int i = 0; i < 2; i++)
                    wmma::load_matrix_sync(fa[i], sA + (wr * 32 + i * 16) * CB_LDA + kk * 16, CB_LDA);
                #pragma unroll
                for (int j = 0; j < 4; j++) {
                    wmma::fragment<wmma::matrix_b, 16, 16, 16, __nv_bfloat16, wmma::row_major> fb;
                    wmma::load_matrix_sync(fb,
                        sB + (kc * 64 + kk * 16) * CB_LDB + wc * 64 + j * 16, CB_LDB);
                    #pragma unroll
                    for (int i = 0; i < 2; i++)
                        wmma::mma_sync(acc[i][j], fa[i], fb, acc[i][j]);
                }
            }
        }

        for (int i = 0; i < 2; i++) {
            int o0 = wr * 32 + i * 16;
            float hm[8];
            #pragma unroll
            for (int jh = 0; jh < 2; jh++) {
                wmma::store_matrix_sync(bufW,      acc[i][jh * 2],     CB_LDU, wmma::mem_row_major);
                wmma::store_matrix_sync(bufW + 16, acc[i][jh * 2 + 1], CB_LDU, wmma::mem_row_major);
                __syncwarp();
                #pragma unroll
                for (int e = 0; e < 8; e++) {
                    int idx = e * 32 + lane;
                    int r = idx >> 4, s = idx & 15;
                    float mv = fmaxf(bufW[r * CB_LDU + 2 * s], bufW[r * CB_LDU + 2 * s + 1]);
                    hm[e] = (jh == 0) ? mv : fmaxf(hm[e], mv);
                }
                __syncwarp();
            }
            __nv_bfloat16* dst = ((mb == 0) ? g_phi : g_gg) + (size_t)tile * I_DIM * KP_DIM;
            const int prow = nb * 2 + wc;
            #pragma unroll
            for (int e = 0; e < 8; e++) {
                int idx = e * 32 + lane;
                int r = idx >> 4, s = idx & 15;
                dst[(o0 + r) * KP_DIM + prow * 16 + s] = __float2bfloat16(hm[e] + BV[o0 + r]);
            }
        }
    }
}

// ---------------------------------------------------------------------------
// Kernel 2 (FUSED theta-conv + attention + out-conv + BN + residual + scatter).
// grid = (qb:8, tile:128), 512 threads (16 warps). Round-9 structure +
// cp.async staging for all pure-copy loads.
// ---------------------------------------------------------------------------
#define AT_LDT 136
#define AT_LDX 136
#define AT_LDWT 264
#define AT_LDS 264
#define AT_LDW 136
#define AT_LDU 36

__global__ __launch_bounds__(512) void attn_kernel(
    const float* __restrict__ x, const float* __restrict__ tb,
    const float* __restrict__ wb,
    const float* __restrict__ gam, const float* __restrict__ bet,
    const float* __restrict__ mean, const float* __restrict__ var,
    float* __restrict__ out)
{
    extern __shared__ char smem[];
    __nv_bfloat16* sT  = reinterpret_cast<__nv_bfloat16*>(smem);             // [128][136]
    __nv_bfloat16* sX  = reinterpret_cast<__nv_bfloat16*>(smem + 34816);     // [256][136] phase0
    __nv_bfloat16* sWt = reinterpret_cast<__nv_bfloat16*>(smem + 104448);    // [128][264] phase0
    __nv_bfloat16* sS  = reinterpret_cast<__nv_bfloat16*>(smem + 34816);     // [128][264] phase1+
    __nv_bfloat16* sG  = reinterpret_cast<__nv_bfloat16*>(smem + 102400);    // [128][264] phase1+
    __nv_bfloat16* sW  = reinterpret_cast<__nv_bfloat16*>(smem + 34816);     // [256][136] phase2
    float*         bufAll = reinterpret_cast<float*>(smem + 172032);         // 16*[16][36]
    float*         sScale = reinterpret_cast<float*>(smem + 208896);         // [256]
    float*         sBase  = reinterpret_cast<float*>(smem + 209920);         // [256]
    const unsigned int smem_u32 = (unsigned int)__cvta_generic_to_shared(smem);
    const unsigned int sWt_u32 = smem_u32 + 104448;
    const unsigned int sS_u32  = smem_u32 + 34816;
    const unsigned int sG_u32  = smem_u32 + 102400;
    const unsigned int sW_u32  = smem_u32 + 34816;

    const int qb   = blockIdx.x;
    const int tile = blockIdx.y;
    const int b = tile >> 4, t = tile & 15;
    const int bs1 = t >> 2, bs2 = t & 3;
    const int tid = threadIdx.x;
    const int warp = tid >> 5, lane = tid & 31;
    const int wr = warp >> 2, wc = warp & 3;
    float* bufW = bufAll + warp * 16 * AT_LDU;

    // BN constants (read only in epilogue; ordering via later barriers)
    if (tid < 256) {
        float sc = gam[tid] * rsqrtf(var[tid] + 1e-5f);
        sScale[tid] = sc;
        sBase[tid]  = (wb[tid] - mean[tid]) * sc + bet[tid];
    }

    // ---- Phase 0: stage x block [256c][128q] bf16 + Wtheta (cp.async) ----
    const float* xtile = x + (size_t)b * C_DIM * 16384 + bs1 * 32 * 128 + bs2 * 32
                       + (size_t)qb * 512;
    #pragma unroll
    for (int it = 0; it < 8; it++) {
        int lin = it * 512 + tid;                   // uint4 among 4096
        int r = lin >> 5, c8 = (lin & 31) * 8;
        cpa16(sWt_u32 + (r * AT_LDWT + c8) * 2, g_twb + r * C_DIM + c8);
    }
    #pragma unroll
    for (int it = 0; it < 16; it++) {
        int lin = it * 512 + tid;                   // float4 idx among 8192
        int r  = lin >> 5;                          // channel 0..255
        int j4 = (lin & 31) * 4;                    // local q (mult of 4)
        float4 v = *reinterpret_cast<const float4*>(
            xtile + (size_t)r * 16384 + (j4 >> 5) * 128 + (j4 & 31));
        __nv_bfloat16* d = sX + r * AT_LDX + j4;
        *reinterpret_cast<__nv_bfloat162*>(d)     = __floats2bfloat162_rn(v.x, v.y);
        *reinterpret_cast<__nv_bfloat162*>(d + 2) = __floats2bfloat162_rn(v.z, v.w);
    }
    CP_COMMIT_WAIT();
    __syncthreads();

    // GEMM0: theta[128i, 128q] = Wt @ x, warp tile 32i x 32q
    {
        wmma::fragment<wmma::accumulator, 16, 16, 16, float> acc0[2][2];
        #pragma unroll
        for (int i = 0; i < 2; i++)
            #pragma unroll
            for (int j = 0; j < 2; j++) wmma::fill_fragment(acc0[i][j], 0.0f);
        #pragma unroll
        for (int kk = 0; kk < 16; kk++) {
            wmma::fragment<wmma::matrix_a, 16, 16, 16, __nv_bfloat16, wmma::row_major> fa[2];
            wmma::fragment<wmma::matrix_b, 16, 16, 16, __nv_bfloat16, wmma::row_major> fb[2];
            #pragma unroll
            for (int i = 0; i < 2; i++)
                wmma::load_matrix_sync(fa[i], sWt + (wr * 32 + i * 16) * AT_LDWT + kk * 16, AT_LDWT);
            #pragma unroll
            for (int j = 0; j < 2; j++)
                wmma::load_matrix_sync(fb[j], sX + (kk * 16) * AT_LDX + wc * 32 + j * 16, AT_LDX);
            #pragma unroll
            for (int i = 0; i < 2; i++)
                #pragma unroll
                for (int j = 0; j < 2; j++)
                    wmma::mma_sync(acc0[i][j], fa[i], fb[j], acc0[i][j]);
        }
        // stream theta + bias -> sT [i][q] bf16
        for (int i = 0; i < 2; i++) {
            int i0 = wr * 32 + i * 16;
            wmma::store_matrix_sync(bufW,      acc0[i][0], AT_LDU, wmma::mem_row_major);
            wmma::store_matrix_sync(bufW + 16, acc0[i][1], AT_LDU, wmma::mem_row_major);
            __syncwarp();
            #pragma unroll
            for (int e = 0; e < 8; e++) {
                int pidx = e * 32 + lane;           // 256 pairs in 16x32
                int r = pidx >> 4, col = (pidx & 15) * 2;
                float bias = tb[i0 + r];
                *reinterpret_cast<__nv_bfloat162*>(sT + (i0 + r) * AT_LDT + wc * 32 + col) =
                    __floats2bfloat162_rn(bufW[r * AT_LDU + col] + bias,
                                          bufW[r * AT_LDU + col + 1] + bias);
            }
            __syncwarp();
        }
    }
    __syncthreads();   // GEMM0 done reading sX/sWt; sT complete

    // ---- Phase 1: stage phi -> sS, g -> sG (cp.async, overlay sX/sWt) ----
    {
        const __nv_bfloat16* ps = g_phi + (size_t)tile * I_DIM * KP_DIM;
        const __nv_bfloat16* gs = g_gg  + (size_t)tile * I_DIM * KP_DIM;
        #pragma unroll
        for (int it = 0; it < 8; it++) {
            int lin = it * 512 + tid;           // uint4 among 4096 (32/row)
            int i = lin >> 5, k8 = (lin & 31) * 8;
            cpa16(sS_u32 + (i * AT_LDS + k8) * 2, ps + i * KP_DIM + k8);
            cpa16(sG_u32 + (i * AT_LDS + k8) * 2, gs + i * KP_DIM + k8);
        }
        CP_COMMIT_WAIT();
    }
    __syncthreads();

    // GEMM1: S[128q, 256k] = theta^T @ phi, warp tile 32x64
    wmma::fragment<wmma::accumulator, 16, 16, 16, float> acc1[2][4];
    #pragma unroll
    for (int i = 0; i < 2; i++)
        #pragma unroll
        for (int j = 0; j < 4; j++) wmma::fill_fragment(acc1[i][j], 0.0f);
    #pragma unroll
    for (int kk = 0; kk < 8; kk++) {
        wmma::fragment<wmma::matrix_a, 16, 16, 16, __nv_bfloat16, wmma::col_major> fa[2];
        #pragma unroll
        for (int i = 0; i < 2; i++)
            wmma::load_matrix_sync(fa[i], sT + (kk * 16) * AT_LDT + wr * 32 + i * 16, AT_LDT);
        #pragma unroll
        for (int j = 0; j < 4; j++) {
            wmma::fragment<wmma::matrix_b, 16, 16, 16, __nv_bfloat16, wmma::row_major> fb;
            wmma::load_matrix_sync(fb, sS + (kk * 16) * AT_LDS + wc * 64 + j * 16, AT_LDS);
            #pragma unroll
            for (int i = 0; i < 2; i++)
                wmma::mma_sync(acc1[i][j], fa[i], fb, acc1[i][j]);
        }
    }
    __syncthreads();   // phi (sS) reads done before S overwrites

    // stream S (fp32 frags) -> bf16 into sS
    for (int i = 0; i < 2; i++) {
        int q0 = wr * 32 + i * 16;
        for (int jh = 0; jh < 2; jh++) {
            int k0 = wc * 64 + jh * 32;
            wmma::store_matrix_sync(bufW,      acc1[i][jh * 2],     AT_LDU, wmma::mem_row_major);
            wmma::store_matrix_sync(bufW + 16, acc1[i][jh * 2 + 1], AT_LDU, wmma::mem_row_major);
            __syncwarp();
            #pragma unroll
            for (int e = 0; e < 8; e++) {
                int pidx = e * 32 + lane;       // 256 pairs in 16x32
                int r = pidx >> 4, col = (pidx & 15) * 2;
                *reinterpret_cast<__nv_bfloat162*>(sS + (q0 + r) * AT_LDS + k0 + col) =
                    __floats2bfloat162_rn(bufW[r * AT_LDU + col], bufW[r * AT_LDU + col + 1]);
            }
            __syncwarp();
        }
    }
    __syncthreads();

    // softmax: 16 warps x 8 rows, k=256, fp32 math on bf16 storage
    for (int rr = 0; rr < 8; rr++) {
        int row = warp * 8 + rr;
        float v[8];
        float m = -1e30f;
        #pragma unroll
        for (int u = 0; u < 8; u++) {
            v[u] = __bfloat162float(sS[row * AT_LDS + u * 32 + lane]);
            m = fmaxf(m, v[u]);
        }
        #pragma unroll
        for (int off = 16; off > 0; off >>= 1) m = fmaxf(m, __shfl_xor_sync(0xffffffffu, m, off));
        float ssum = 0.f;
        #pragma unroll
        for (int u = 0; u < 8; u++) { v[u] = __expf(v[u] - m); ssum += v[u]; }
        #pragma unroll
        for (int off = 16; off > 0; off >>= 1) ssum += __shfl_xor_sync(0xffffffffu, ssum, off);
        float inv = 1.0f / ssum;
        #pragma unroll
        for (int u = 0; u < 8; u++)
            sS[row * AT_LDS + u * 32 + lane] = __float2bfloat16(v[u] * inv);
    }
    __syncthreads();

    // GEMM2: y[128q, 128io] = F @ g^T, warp tile 32x32
    wmma::fragment<wmma::accumulator, 16, 16, 16, float> acc2[2][2];
    #pragma unroll
    for (int i = 0; i < 2; i++)
        #pragma unroll
        for (int j = 0; j < 2; j++) wmma::fill_fragment(acc2[i][j], 0.0f);
    #pragma unroll
    for (int kk = 0; kk < 16; kk++) {
        wmma::fragment<wmma::matrix_a, 16, 16, 16, __nv_bfloat16, wmma::row_major> fa[2];
        wmma::fragment<wmma::matrix_b, 16, 16, 16, __nv_bfloat16, wmma::col_major> fb[2];
        #pragma unroll
        for (int i = 0; i < 2; i++)
            wmma::load_matrix_sync(fa[i], sS + (wr * 32 + i * 16) * AT_LDS + kk * 16, AT_LDS);
        #pragma unroll
        for (int j = 0; j < 2; j++)
            wmma::load_matrix_sync(fb[j], sG + (wc * 32 + j * 16) * AT_LDS + kk * 16, AT_LDS);
        #pragma unroll
        for (int i = 0; i < 2; i++)
            #pragma unroll
            for (int j = 0; j < 2; j++)
                wmma::mma_sync(acc2[i][j], fa[i], fb[j], acc2[i][j]);
    }
    __syncthreads();   // all reads of sS/sG/sT done; safe to overlay

    // stage W (cp.async) + stream y -> sT bf16 [128q][128io]
    #pragma unroll
    for (int it = 0; it < 8; it++) {
        int lin = it * 512 + tid;               // uint4 among 4096
        int r = lin >> 4, c8 = (lin & 15) * 8;
        cpa16(sW_u32 + (r * AT_LDW + c8) * 2, g_wwb + r * I_DIM + c8);
    }
    {
        int io0 = wc * 32;
        for (int i = 0; i < 2; i++) {
            int q0 = wr * 32 + i * 16;
            wmma::store_matrix_sync(bufW,      acc2[i][0], AT_LDU, wmma::mem_row_major);
            wmma::store_matrix_sync(bufW + 16, acc2[i][1], AT_LDU, wmma::mem_row_major);
            __syncwarp();
            #pragma unroll
            for (int e = 0; e < 8; e++) {
                int pidx = e * 32 + lane;
                int r = pidx >> 4, col = (pidx & 15) * 2;
                *reinterpret_cast<__nv_bfloat162*>(sT + (q0 + r) * AT_LDT + io0 + col) =
                    __floats2bfloat162_rn(bufW[r * AT_LDU + col], bufW[r * AT_LDU + col + 1]);
            }
            __syncwarp();
        }
    }
    CP_COMMIT_WAIT();
    __syncthreads();

    // GEMM3: wy[256o, 128q] = W @ y^T, warp tile 64o x 32q
    wmma::fragment<wmma::accumulator, 16, 16, 16, float> acc3[4][2];
    #pragma unroll
    for (int i = 0; i < 4; i++)
        #pragma unroll
        for (int j = 0; j < 2; j++) wmma::fill_fragment(acc3[i][j], 0.0f);
    #pragma unroll
    for (int kk = 0; kk < 8; kk++) {
        wmma::fragment<wmma::matrix_b, 16, 16, 16, __nv_bfloat16, wmma::col_major> fb[2];
        #pragma unroll
        for (int j = 0; j < 2; j++)
            wmma::load_matrix_sync(fb[j], sT + (wc * 32 + j * 16) * AT_LDT + kk * 16, AT_LDT);
        #pragma unroll
        for (int i = 0; i < 4; i++) {
            wmma::fragment<wmma::matrix_a, 16, 16, 16, __nv_bfloat16, wmma::row_major> fa;
            wmma::load_matrix_sync(fa, sW + (wr * 64 + i * 16) * AT_LDW + kk * 16, AT_LDW);
            #pragma unroll
            for (int j = 0; j < 2; j++)
                wmma::mma_sync(acc3[i][j], fa, fb[j], acc3[i][j]);
        }
    }

    // epilogue: BN + residual + permuted (fully coalesced) store.
    const float* xrow = x + (size_t)b * C_DIM * 16384 + bs1 * 32 * 128 + bs2 * 32
                      + (size_t)qb * 512;
    float* obase = out + (size_t)b * C_DIM * 16384;
    const int lq = wc * 32 + lane;
    const int xoff = (lq >> 5) * 128 + (lq & 31);   // row-major offset within tile
    for (int i = 0; i < 4; i++) {
        int o0 = wr * 64 + i * 16;
        wmma::store_matrix_sync(bufW,      acc3[i][0], AT_LDU, wmma::mem_row_major);
        wmma::store_matrix_sync(bufW + 16, acc3[i][1], AT_LDU, wmma::mem_row_major);
        __syncwarp();
        #pragma unroll
        for (int e = 0; e < 16; e++) {
            int o = o0 + e;
            float v = bufW[e * AT_LDU + lane] * sScale[o] + sBase[o]
                    + xrow[(size_t)o * 16384 + xoff];
            int co = t * 16 + (o >> 4);
            int oh = (o & 15) * 8 + qb;
            obase[(size_t)co * 16384 + (size_t)oh * 128 + lq] = v;
        }
        __syncwarp();
    }
}

// ---------------------------------------------------------------------------
extern "C" void kernel_launch(void* const* d_in, const int* in_sizes, int n_in,
                              void* d_out, int out_size)
{
    const float* x    = (const float*)d_in[0];
    const float* tw   = (const float*)d_in[1];
    const float* tb   = (const float*)d_in[2];
    const float* pw   = (const float*)d_in[3];
    const float* pb   = (const float*)d_in[4];
    const float* gw   = (const float*)d_in[5];
    const float* gb   = (const float*)d_in[6];
    const float* ww   = (const float*)d_in[7];
    const float* wb   = (const float*)d_in[8];
    const float* gam  = (const float*)d_in[9];
    const float* bet  = (const float*)d_in[10];
    const float* mean = (const float*)d_in[11];
    const float* var  = (const float*)d_in[12];
    float* out = (float*)d_out;

    cudaFuncSetAttribute(conv2_kernel, cudaFuncAttributeMaxDynamicSharedMemorySize, 106496);
    cudaFuncSetAttribute(attn_kernel,  cudaFuncAttributeMaxDynamicSharedMemorySize, 210944);

    prep_kernel <<<128, 256>>>(tw, pw, gw, ww);
    conv2_kernel<<<dim3(8, NTILES), 256, 106496>>>(x, pb, gb);
    attn_kernel <<<dim3(8, NTILES), 512, 210944>>>(x, tb, wb, gam, bet, mean, var, out);
}